// round 9
// baseline (speedup 1.0000x reference)
#include <cuda_runtime.h>
#include <float.h>

// ROI max pooling, exact integer-bin partition (matches reference):
//   cell (py,px) of roi (y0,x0,h,w) covers rows [y0 + py*h/7, y0 + (py+1)*h/7)
//   and cols [x0 + px*w/7, x0 + (px+1)*w/7). h,w >= 7 so cells are non-empty.
//
// Shapes: feature_map [B=2, H=38, W=38, C=512] f32, rois [B=2, N=64, 4] i32,
// out [B, N, 7, 7, C] f32.
//
// R4 -> R5: tail/imbalance bound (occ 31%, issue 31%, caches ~35%). 4 warps
// per (cell, channel-half); the cell's cw*ch pixels are dealt cyclically to
// warps (warp k: pixels k, k+4, ...), partial maxes combined via smem. Big
// cells' critical path drops 4x (36 -> 9 px/warp); 128-thr blocks restore
// full-occupancy headroom.

#define H_DIM 38
#define W_DIM 38
#define C4 128           // C/4 float4 groups per pixel
#define POOL 7
#define NWARP 4

__device__ __forceinline__ void fmax4(float4& m, const float4 v) {
    m.x = fmaxf(m.x, v.x);
    m.y = fmaxf(m.y, v.y);
    m.z = fmaxf(m.z, v.z);
    m.w = fmaxf(m.w, v.w);
}

__device__ __forceinline__ float4 fmax4v(const float4 a, const float4 b) {
    return make_float4(fmaxf(a.x, b.x), fmaxf(a.y, b.y),
                       fmaxf(a.z, b.z), fmaxf(a.w, b.w));
}

__global__ __launch_bounds__(128) void roi_pool_kernel(
    const float4* __restrict__ fm,   // [B, H, W, C/4] as float4
    const int*    __restrict__ rois, // [B*N, 4] (y, x, h, w)
    float4*       __restrict__ out,  // [B*N, 49, C/4] as float4
    int n_per_b)                     // N (rois per batch)
{
    __shared__ float4 sm[NWARP][2][32];

    const int cell = blockIdx.x;        // roi*49 + py*7 + px
    const int px   = cell % POOL;
    const int py   = (cell / POOL) % POOL;
    const int roi  = cell / (POOL * POOL);
    const int b    = roi / n_per_b;

    const int4 r = __ldg((const int4*)(rois + roi * 4));
    const int y0 = r.x, x0 = r.y, h = r.z, w = r.w;

    const int ys = y0 + (py * h) / POOL;
    const int ye = y0 + ((py + 1) * h) / POOL;
    const int xs = x0 + (px * w) / POOL;
    const int xe = x0 + ((px + 1) * w) / POOL;
    const int cw = xe - xs;             // 1..6
    const int ch = ye - ys;             // 1..6

    const int warp = threadIdx.x >> 5;
    const int lane = threadIdx.x & 31;

    // channel half: slots [gy*64, gy*64+64); thread owns c and c+32
    const int c = (blockIdx.y << 6) + lane;
    const float4* base = fm + (((size_t)b * H_DIM + ys) * W_DIM + xs) * C4 + c;

    float4 m0 = make_float4(-FLT_MAX, -FLT_MAX, -FLT_MAX, -FLT_MAX);
    float4 m1 = m0;

    // cyclic pixel assignment: warp k handles linear pixels k, k+4, ...
    int dy = 0, dx = warp;
    while (dx >= cw) { dx -= cw; ++dy; }

    while (dy < ch) {
        // pixel 0
        const int yA = dy, xA = dx;
        dx += NWARP;
        while (dx >= cw) { dx -= cw; ++dy; }
        const bool have2 = dy < ch;
        const int yB = dy, xB = dx;
        if (have2) {
            dx += NWARP;
            while (dx >= cw) { dx -= cw; ++dy; }
        }

        const float4* pA = base + (size_t)(yA * W_DIM + xA) * C4;
        float4 a0 = __ldg(pA);
        float4 a1 = __ldg(pA + 32);
        if (have2) {
            const float4* pB = base + (size_t)(yB * W_DIM + xB) * C4;
            float4 b0 = __ldg(pB);
            float4 b1 = __ldg(pB + 32);
            fmax4(m0, b0); fmax4(m1, b1);
        }
        fmax4(m0, a0); fmax4(m1, a1);
    }

    sm[warp][0][lane] = m0;
    sm[warp][1][lane] = m1;
    __syncthreads();

    // threads 0..31 reduce m0 slots, threads 32..63 reduce m1 slots
    if (threadIdx.x < 64) {
        const int half = warp;          // 0 -> m0, 1 -> m1
        float4 f = fmax4v(fmax4v(sm[0][half][lane], sm[1][half][lane]),
                          fmax4v(sm[2][half][lane], sm[3][half][lane]));
        out[(size_t)cell * C4 + (blockIdx.y << 6) + half * 32 + lane] = f;
    }
}

extern "C" void kernel_launch(void* const* d_in, const int* in_sizes, int n_in,
                              void* d_out, int out_size) {
    const float4* fm   = (const float4*)d_in[0];
    const int*    rois = (const int*)d_in[1];
    float4*       out  = (float4*)d_out;

    const int n_rois  = in_sizes[1] / 4;     // B*N = 128
    const int B       = 2;                   // fixed per problem shapes
    const int n_per_b = n_rois / B;          // N = 64

    dim3 grid(n_rois * POOL * POOL, 2);      // 6272 cells x 2 channel halves
    roi_pool_kernel<<<grid, 128>>>(fm, rois, out, n_per_b);
}

// round 10
// speedup vs baseline: 1.9730x; 1.9730x over previous
#include <cuda_runtime.h>
#include <float.h>

// ROI max pooling, exact integer-bin partition (matches reference):
//   cell (py,px) of roi (y0,x0,h,w) covers rows [y0 + py*h/7, y0 + (py+1)*h/7)
//   and cols [x0 + px*w/7, x0 + (px+1)*w/7). h,w >= 7 so cells are non-empty.
//
// Shapes: feature_map [B=2, H=38, W=38, C=512] f32, rois [B=2, N=64, 4] i32,
// out [B, N, 7, 7, C] f32.
//
// R8 -> R9: revert smem/4-warp split (ALU+smem overhead doubled time). Back
// to R4 shell (1 warp per (cell, channel-half), grid (6272,2)) but with
// 8-pixel flattened unroll: linear pixel idx -> (dy,dx) via exact magic-div
// (cw<=6, idx<36), out-of-range slots clamped to last pixel (dup loads are
// harmless for max, L1 hits). 16 independent LDG.128 in flight per warp
// (2x R4) to cover the ~900cyc effective L2/queue latency.

#define H_DIM 38
#define W_DIM 38
#define C4 128           // C/4 float4 groups per pixel
#define POOL 7

__device__ __forceinline__ void fmax4(float4& m, const float4 v) {
    m.x = fmaxf(m.x, v.x);
    m.y = fmaxf(m.y, v.y);
    m.z = fmaxf(m.z, v.z);
    m.w = fmaxf(m.w, v.w);
}

__global__ __launch_bounds__(32) void roi_pool_kernel(
    const float4* __restrict__ fm,   // [B, H, W, C/4] as float4
    const int*    __restrict__ rois, // [B*N, 4] (y, x, h, w)
    float4*       __restrict__ out,  // [B*N, 49, C/4] as float4
    int n_per_b)                     // N (rois per batch)
{
    const int cell = blockIdx.x;        // roi*49 + py*7 + px
    const int px   = cell % POOL;
    const int py   = (cell / POOL) % POOL;
    const int roi  = cell / (POOL * POOL);
    const int b    = roi / n_per_b;

    const int4 r = __ldg((const int4*)(rois + roi * 4));
    const int y0 = r.x, x0 = r.y, h = r.z, w = r.w;

    const int ys = y0 + (py * h) / POOL;
    const int ye = y0 + ((py + 1) * h) / POOL;
    const int xs = x0 + (px * w) / POOL;
    const int xe = x0 + ((px + 1) * w) / POOL;
    const int cw   = xe - xs;           // 1..6
    const int npix = cw * (ye - ys);    // 1..36

    // exact floor(idx/cw) for idx < 36, cw <= 6: magic = ceil(2^16/cw)
    const unsigned magic = (65536u + (unsigned)cw - 1u) / (unsigned)cw;

    // channel half: slots [gy*64, gy*64+64); thread owns c and c+32
    const int c = (blockIdx.y << 6) + threadIdx.x;
    const float4* base = fm + (((size_t)b * H_DIM + ys) * W_DIM + xs) * C4 + c;

    float4 m0 = make_float4(-FLT_MAX, -FLT_MAX, -FLT_MAX, -FLT_MAX);
    float4 m1 = m0;

    const int last = npix - 1;

    for (int pbase = 0; pbase < npix; pbase += 8) {
        const float4* p[8];
#pragma unroll
        for (int k = 0; k < 8; ++k) {
            int idx = pbase + k;
            idx = idx < last ? idx : last;          // clamp: dup of last pixel
            const int dy = (int)(((unsigned)idx * magic) >> 16);
            const int dx = idx - dy * cw;
            p[k] = base + (size_t)(dy * W_DIM + dx) * C4;
        }
        float4 v0[8], v1[8];
#pragma unroll
        for (int k = 0; k < 8; ++k) {               // 16 independent LDG.128
            v0[k] = __ldg(p[k]);
            v1[k] = __ldg(p[k] + 32);
        }
#pragma unroll
        for (int k = 0; k < 8; ++k) {
            fmax4(m0, v0[k]);
            fmax4(m1, v1[k]);
        }
    }

    float4* o = out + (size_t)cell * C4 + c;
    o[0]  = m0;
    o[32] = m1;
}

extern "C" void kernel_launch(void* const* d_in, const int* in_sizes, int n_in,
                              void* d_out, int out_size) {
    const float4* fm   = (const float4*)d_in[0];
    const int*    rois = (const int*)d_in[1];
    float4*       out  = (float4*)d_out;

    const int n_rois  = in_sizes[1] / 4;     // B*N = 128
    const int B       = 2;                   // fixed per problem shapes
    const int n_per_b = n_rois / B;          // N = 64

    dim3 grid(n_rois * POOL * POOL, 2);      // 6272 cells x 2 channel halves
    roi_pool_kernel<<<grid, 32>>>(fm, rois, out, n_per_b);
}